// round 2
// baseline (speedup 1.0000x reference)
#include <cuda_runtime.h>
#include <math.h>

#define NPTS 4096
#define BATCH 4
#define CCH 128
#define KNN 10
#define RTOT (BATCH * NPTS)

// ---------------- scratch (device globals) ----------------
__device__ float g_Wc1[256 * 128];
__device__ float g_Wc2[512 * 128];
__device__ float g_xcat[RTOT * 512];       // [r][512]: 0..127 x0 | 128..255 x1 | 256..511 x2
__device__ float g_UV1[RTOT * 256];        // [r][256]: U 0..127 | V 128..255
__device__ float g_UV2[RTOT * 512];        // [r][512]: U 0..255 | V 256..511
__device__ float g_y3[RTOT * 128];
__device__ int   g_idx[RTOT * KNN];
__device__ float g_kpd[BATCH * 4 * NPTS * KNN];
__device__ int   g_kpi[BATCH * 4 * NPTS * KNN];
__device__ float g_psum[BATCH * 512 * 256];
__device__ float g_pssq[BATCH * 512 * 256];
__device__ float g_mu[BATCH * 256];
__device__ float g_rstd[BATCH * 256];

// ---------------- weight prep ----------------
__global__ void prep_w(const float* __restrict__ W1, const float* __restrict__ W2,
                       float* __restrict__ Wc1, float* __restrict__ Wc2) {
    int i = blockIdx.x * blockDim.x + threadIdx.x;
    if (i < 256 * 128) {
        int o = i / 128, c = i % 128;
        if (o < 128) Wc1[i] = W1[o * 256 + c] - W1[o * 256 + 128 + c];
        else         Wc1[i] = W1[(o - 128) * 256 + 128 + c];
    }
    if (i < 512 * 128) {
        int o = i / 128, c = i % 128;
        if (o < 256) Wc2[i] = W2[o * 256 + c] - W2[o * 256 + 128 + c];
        else         Wc2[i] = W2[(o - 256) * 256 + 128 + c];
    }
}

// ---------------- transpose feats [b][c][n] -> xcat[r][c] (cols 0..127) ----------------
__global__ void trans_in(const float* __restrict__ F, float* __restrict__ xcat) {
    __shared__ float sm[32][33];
    int b = blockIdx.z, n0 = blockIdx.x * 32, c0 = blockIdx.y * 32;
    int tx = threadIdx.x, ty = threadIdx.y;
#pragma unroll
    for (int q = 0; q < 4; q++)   // sm[c_local][n_local]
        sm[ty + q * 8][tx] = F[((size_t)b * CCH + c0 + ty + q * 8) * NPTS + n0 + tx];
    __syncthreads();
#pragma unroll
    for (int q = 0; q < 4; q++) {
        int n = n0 + ty + q * 8;
        xcat[((size_t)(b * NPTS + n)) * 512 + c0 + tx] = sm[tx][ty + q * 8];
    }
}

// ---------------- KNN pass1: per-slice top-10 ----------------
__global__ void knn_part(const float* __restrict__ coords,
                         float* __restrict__ pd, int* __restrict__ pi) {
    int b = blockIdx.z, s = blockIdx.y;
    int n = blockIdx.x * 256 + threadIdx.x;
    const float* cb = coords + (size_t)b * 3 * NPTS;
    __shared__ float sx[1024], sy[1024], sz[1024], ss[1024];
    int base = s * 1024;
    for (int j = threadIdx.x; j < 1024; j += 256) {
        float x = cb[base + j], y = cb[NPTS + base + j], z = cb[2 * NPTS + base + j];
        sx[j] = x; sy[j] = y; sz[j] = z; ss[j] = x * x + y * y + z * z;
    }
    __syncthreads();
    float qx = cb[n], qy = cb[NPTS + n], qz = cb[2 * NPTS + n];
    float qs = qx * qx + qy * qy + qz * qz;
    float dist[KNN]; int ind[KNN];
#pragma unroll
    for (int i = 0; i < KNN; i++) { dist[i] = 3.4e38f; ind[i] = 0x7fffffff; }
    float worst = 3.4e38f;
    for (int j = 0; j < 1024; j++) {
        int jj = base + j;
        float d = qs + ss[j] - 2.f * (qx * sx[j] + qy * sy[j] + qz * sz[j]);
        d = fmaxf(d, 1e-12f);
        if (d < worst && jj != n) {
            int p = KNN - 1;
            while (p > 0 && dist[p - 1] > d) { dist[p] = dist[p - 1]; ind[p] = ind[p - 1]; p--; }
            dist[p] = d; ind[p] = jj;
            worst = dist[KNN - 1];
        }
    }
    size_t off = ((size_t)(b * 4 + s) * NPTS + n) * KNN;
#pragma unroll
    for (int i = 0; i < KNN; i++) { pd[off + i] = dist[i]; pi[off + i] = ind[i]; }
}

// ---------------- KNN merge: 4 sorted lists -> final 10 ----------------
__global__ void knn_merge(const float* __restrict__ pd, const int* __restrict__ pi,
                          int* __restrict__ out) {
    int t = blockIdx.x * 256 + threadIdx.x;
    if (t >= RTOT) return;
    int b = t >> 12, n = t & (NPTS - 1);
    const float* pdp[4]; const int* pip[4]; int pos[4] = {0, 0, 0, 0};
#pragma unroll
    for (int s = 0; s < 4; s++) {
        size_t off = ((size_t)(b * 4 + s) * NPTS + n) * KNN;
        pdp[s] = pd + off; pip[s] = pi + off;
    }
    int* op = out + (size_t)t * KNN;
#pragma unroll
    for (int r = 0; r < KNN; r++) {
        float best = 3.5e38f; int bs = 0, bidx = 0x7fffffff;
#pragma unroll
        for (int s = 0; s < 4; s++) {
            float dv = pdp[s][pos[s]];
            int iv = pip[s][pos[s]];
            if (dv < best || (dv == best && iv < bidx)) { best = dv; bs = s; bidx = iv; }
        }
        op[r] = bidx; pos[bs]++;
    }
}

// ---------------- fp32 NT GEMM: O[r][m] = sum_c X[r][coff+c] * W[m][c] ----------------
// 128x128 tile, 256 threads, 8x8 micro.
__global__ void gemm128(const float* __restrict__ X, int ldx, int coff,
                        const float* __restrict__ W,
                        float* __restrict__ O, int ldo, int Kd) {
    __shared__ float Xs[16][132];
    __shared__ float Ws[16][132];
    int tid = threadIdx.x;
    int r0 = blockIdx.x * 128, m0 = blockIdx.y * 128;
    int thr_r = tid & 15, thr_m = tid >> 4;
    float acc[8][8] = {};
    const float* Xg = X + (size_t)r0 * ldx + coff;
    const float* Wg = W + (size_t)m0 * Kd;

    for (int k0 = 0; k0 < Kd; k0 += 16) {
#pragma unroll
        for (int t = 0; t < 2; t++) {
            int f = tid * 2 + t;
            int rr = f >> 2, kc = (f & 3) * 4;
            float4 v = *(const float4*)&Xg[(size_t)rr * ldx + k0 + kc];
            Xs[kc + 0][rr] = v.x; Xs[kc + 1][rr] = v.y;
            Xs[kc + 2][rr] = v.z; Xs[kc + 3][rr] = v.w;
            float4 w = *(const float4*)&Wg[(size_t)rr * Kd + k0 + kc];
            Ws[kc + 0][rr] = w.x; Ws[kc + 1][rr] = w.y;
            Ws[kc + 2][rr] = w.z; Ws[kc + 3][rr] = w.w;
        }
        __syncthreads();
#pragma unroll
        for (int kk = 0; kk < 16; kk++) {
            float xr[8], wm[8];
            *(float4*)&xr[0] = *(const float4*)&Xs[kk][thr_r * 8];
            *(float4*)&xr[4] = *(const float4*)&Xs[kk][thr_r * 8 + 4];
            *(float4*)&wm[0] = *(const float4*)&Ws[kk][thr_m * 8];
            *(float4*)&wm[4] = *(const float4*)&Ws[kk][thr_m * 8 + 4];
#pragma unroll
            for (int i = 0; i < 8; i++)
#pragma unroll
                for (int j = 0; j < 8; j++)
                    acc[i][j] += xr[i] * wm[j];
        }
        __syncthreads();
    }
#pragma unroll
    for (int i = 0; i < 8; i++) {
        float* orow = O + (size_t)(r0 + thr_r * 8 + i) * ldo + m0 + thr_m * 8;
        *(float4*)&orow[0] = make_float4(acc[i][0], acc[i][1], acc[i][2], acc[i][3]);
        *(float4*)&orow[4] = make_float4(acc[i][4], acc[i][5], acc[i][6], acc[i][7]);
    }
}

// ---------------- EdgeConv gather + max_k + stats partials (point-major) ----------------
// UV rows [r][2C]; writes unnormalized max to xcat cols [outCol, outCol+C);
// per-warp column partial sums to psum/pssq (stride 256 per warp slot... C floats used).
template <int C>
__global__ void edge_kernel(const float* __restrict__ UV, const int* __restrict__ idx,
                            float* __restrict__ xcat, int outCol,
                            float* __restrict__ psum, float* __restrict__ pssq) {
    const int RS = 2 * C;
    const int J = C / 128;
    int b = blockIdx.y;
    int warp = threadIdx.x >> 5, lane = threadIdx.x & 31;
    int qbase = blockIdx.x * 64 + warp * 8;
    const float* UVb = UV + (size_t)b * NPTS * RS;
    const int* idb = idx + (size_t)b * NPTS * KNN;

    float sum[4 * J], ssq[4 * J];
#pragma unroll
    for (int e = 0; e < 4 * J; e++) { sum[e] = 0.f; ssq[e] = 0.f; }

    for (int i = 0; i < 8; i++) {
        int q = qbase + i;
        const float* urow = UVb + (size_t)q * RS;
        float4 u[J], m[J];
#pragma unroll
        for (int j = 0; j < J; j++) {
            u[j] = *(const float4*)&urow[j * 128 + 4 * lane];
            m[j] = make_float4(-3.4e38f, -3.4e38f, -3.4e38f, -3.4e38f);
        }
        int jn[KNN];
#pragma unroll
        for (int kk = 0; kk < KNN; kk++) jn[kk] = idb[q * KNN + kk];
#pragma unroll
        for (int kk = 0; kk < KNN; kk++) {
            const float* vrow = UVb + (size_t)jn[kk] * RS + C;
#pragma unroll
            for (int j = 0; j < J; j++) {
                float4 v = *(const float4*)&vrow[j * 128 + 4 * lane];
                float y0 = u[j].x + v.x, y1 = u[j].y + v.y;
                float y2 = u[j].z + v.z, y3 = u[j].w + v.w;
                m[j].x = fmaxf(m[j].x, y0); m[j].y = fmaxf(m[j].y, y1);
                m[j].z = fmaxf(m[j].z, y2); m[j].w = fmaxf(m[j].w, y3);
                sum[j * 4 + 0] += y0; ssq[j * 4 + 0] += y0 * y0;
                sum[j * 4 + 1] += y1; ssq[j * 4 + 1] += y1 * y1;
                sum[j * 4 + 2] += y2; ssq[j * 4 + 2] += y2 * y2;
                sum[j * 4 + 3] += y3; ssq[j * 4 + 3] += y3 * y3;
            }
        }
        float* orow = xcat + (size_t)(b * NPTS + q) * 512 + outCol;
#pragma unroll
        for (int j = 0; j < J; j++)
            *(float4*)&orow[j * 128 + 4 * lane] = m[j];
    }
    int w = blockIdx.x * 8 + warp;   // 0..511
    float* ps = psum + (size_t)(b * 512 + w) * 256;
    float* pq = pssq + (size_t)(b * 512 + w) * 256;
#pragma unroll
    for (int j = 0; j < J; j++) {
        *(float4*)&ps[j * 128 + 4 * lane] = make_float4(sum[j * 4], sum[j * 4 + 1], sum[j * 4 + 2], sum[j * 4 + 3]);
        *(float4*)&pq[j * 128 + 4 * lane] = make_float4(ssq[j * 4], ssq[j * 4 + 1], ssq[j * 4 + 2], ssq[j * 4 + 3]);
    }
}

// ---------------- column partial sums of y3 (for final instance norm) ----------------
__global__ void colsum128(const float* __restrict__ Y,
                          float* __restrict__ psum, float* __restrict__ pssq) {
    int b = blockIdx.y;
    int warp = threadIdx.x >> 5, lane = threadIdx.x & 31;
    int qbase = blockIdx.x * 64 + warp * 8;
    float s[4] = {0, 0, 0, 0}, s2[4] = {0, 0, 0, 0};
    for (int i = 0; i < 8; i++) {
        float4 v = *(const float4*)&Y[(size_t)(b * NPTS + qbase + i) * 128 + 4 * lane];
        s[0] += v.x; s2[0] += v.x * v.x;
        s[1] += v.y; s2[1] += v.y * v.y;
        s[2] += v.z; s2[2] += v.z * v.z;
        s[3] += v.w; s2[3] += v.w * v.w;
    }
    int w = blockIdx.x * 8 + warp;
    *(float4*)&psum[(size_t)(b * 512 + w) * 256 + 4 * lane] = make_float4(s[0], s[1], s[2], s[3]);
    *(float4*)&pssq[(size_t)(b * 512 + w) * 256 + 4 * lane] = make_float4(s2[0], s2[1], s2[2], s2[3]);
}

// ---------------- reduce partials -> mu, rstd (deterministic, double) ----------------
__global__ void reduce_stats(const float* __restrict__ psum, const float* __restrict__ pssq,
                             float* __restrict__ mu, float* __restrict__ rstd, double cnt) {
    int o = blockIdx.x, b = blockIdx.y, t = threadIdx.x;
    __shared__ double sr[128], sr2[128];
    double s = 0.0, s2 = 0.0;
    for (int w = t; w < 512; w += 128) {
        s  += (double)psum[(size_t)(b * 512 + w) * 256 + o];
        s2 += (double)pssq[(size_t)(b * 512 + w) * 256 + o];
    }
    sr[t] = s; sr2[t] = s2;
    __syncthreads();
    for (int st = 64; st > 0; st >>= 1) {
        if (t < st) { sr[t] += sr[t + st]; sr2[t] += sr2[t + st]; }
        __syncthreads();
    }
    if (t == 0) {
        double m = sr[0] / cnt;
        double var = sr2[0] / cnt - m * m;
        mu[b * 256 + o] = (float)m;
        rstd[b * 256 + o] = (float)(1.0 / sqrt(var + 1e-5));
    }
}

// ---------------- apply instance norm + lrelu in place on xcat col block ----------------
__global__ void apply_norm(float* __restrict__ xcat, int outCol, int C,
                           const float* __restrict__ mu, const float* __restrict__ rstd) {
    int i = blockIdx.x * 256 + threadIdx.x;
    int perRow = C / 4;
    int r = i / perRow, cq = i % perRow;
    if (r >= RTOT) return;
    int b = r >> 12;
    float4* p = (float4*)&xcat[(size_t)r * 512 + outCol + cq * 4];
    float4 v = *p;
    float4 m4 = *(const float4*)&mu[b * 256 + cq * 4];
    float4 r4 = *(const float4*)&rstd[b * 256 + cq * 4];
    float a = (v.x - m4.x) * r4.x; v.x = a >= 0.f ? a : 0.2f * a;
    a = (v.y - m4.y) * r4.y; v.y = a >= 0.f ? a : 0.2f * a;
    a = (v.z - m4.z) * r4.z; v.z = a >= 0.f ? a : 0.2f * a;
    a = (v.w - m4.w) * r4.w; v.w = a >= 0.f ? a : 0.2f * a;
    *p = v;
}

// ---------------- final: normalize + lrelu + transpose y3[r][c] -> out[b][c][n] ----------------
__global__ void trans_out(const float* __restrict__ Y, const float* __restrict__ mu,
                          const float* __restrict__ rstd, float* __restrict__ out) {
    __shared__ float sm[32][33];
    int b = blockIdx.z, n0 = blockIdx.x * 32, c0 = blockIdx.y * 32;
    int tx = threadIdx.x, ty = threadIdx.y;
#pragma unroll
    for (int q = 0; q < 4; q++) {   // sm[n_local][c_local]
        int n = n0 + ty + q * 8;
        sm[ty + q * 8][tx] = Y[(size_t)(b * NPTS + n) * 128 + c0 + tx];
    }
    __syncthreads();
#pragma unroll
    for (int q = 0; q < 4; q++) {
        int c = c0 + ty + q * 8;
        float m = mu[b * 256 + c], rr = rstd[b * 256 + c];
        float v = (sm[tx][ty + q * 8] - m) * rr;
        out[((size_t)b * 128 + c) * NPTS + n0 + tx] = v >= 0.f ? v : 0.2f * v;
    }
}

// ---------------- launch ----------------
extern "C" void kernel_launch(void* const* d_in, const int* in_sizes, int n_in,
                              void* d_out, int out_size) {
    const float* coords = (const float*)d_in[0];
    const float* feats  = (const float*)d_in[1];
    const float* W1     = (const float*)d_in[2];
    const float* W2     = (const float*)d_in[3];
    const float* W3     = (const float*)d_in[4];
    float* out = (float*)d_out;

    float *Wc1, *Wc2, *xcat, *UV1, *UV2, *y3, *kpd, *psum, *pssq, *mu, *rstd;
    int *idx, *kpi;
    cudaGetSymbolAddress((void**)&Wc1,  g_Wc1);
    cudaGetSymbolAddress((void**)&Wc2,  g_Wc2);
    cudaGetSymbolAddress((void**)&xcat, g_xcat);
    cudaGetSymbolAddress((void**)&UV1,  g_UV1);
    cudaGetSymbolAddress((void**)&UV2,  g_UV2);
    cudaGetSymbolAddress((void**)&y3,   g_y3);
    cudaGetSymbolAddress((void**)&idx,  g_idx);
    cudaGetSymbolAddress((void**)&kpd,  g_kpd);
    cudaGetSymbolAddress((void**)&kpi,  g_kpi);
    cudaGetSymbolAddress((void**)&psum, g_psum);
    cudaGetSymbolAddress((void**)&pssq, g_pssq);
    cudaGetSymbolAddress((void**)&mu,   g_mu);
    cudaGetSymbolAddress((void**)&rstd, g_rstd);

    prep_w<<<256, 256>>>(W1, W2, Wc1, Wc2);
    trans_in<<<dim3(NPTS / 32, CCH / 32, BATCH), dim3(32, 8)>>>(feats, xcat);
    knn_part<<<dim3(NPTS / 256, 4, BATCH), 256>>>(coords, kpd, kpi);
    knn_merge<<<RTOT / 256, 256>>>(kpd, kpi, idx);

    // stage 1
    gemm128<<<dim3(RTOT / 128, 256 / 128), 256>>>(xcat, 512, 0, Wc1, UV1, 256, 128);
    edge_kernel<128><<<dim3(NPTS / 64, BATCH), 256>>>(UV1, idx, xcat, 128, psum, pssq);
    reduce_stats<<<dim3(128, BATCH), 128>>>(psum, pssq, mu, rstd, (double)NPTS * KNN);
    apply_norm<<<RTOT * 32 / 256, 256>>>(xcat, 128, 128, mu, rstd);

    // stage 2
    gemm128<<<dim3(RTOT / 128, 512 / 128), 256>>>(xcat, 512, 128, Wc2, UV2, 512, 128);
    edge_kernel<256><<<dim3(NPTS / 64, BATCH), 256>>>(UV2, idx, xcat, 256, psum, pssq);
    reduce_stats<<<dim3(256, BATCH), 128>>>(psum, pssq, mu, rstd, (double)NPTS * KNN);
    apply_norm<<<RTOT * 64 / 256, 256>>>(xcat, 256, 256, mu, rstd);

    // stage 3
    gemm128<<<dim3(RTOT / 128, 128 / 128), 256>>>(xcat, 512, 0, W3, y3, 128, 512);
    colsum128<<<dim3(NPTS / 64, BATCH), 256>>>(y3, psum, pssq);
    reduce_stats<<<dim3(128, BATCH), 128>>>(psum, pssq, mu, rstd, (double)NPTS);
    trans_out<<<dim3(NPTS / 32, 128 / 32, BATCH), dim3(32, 8)>>>(y3, mu, rstd, out);
}